// round 12
// baseline (speedup 1.0000x reference)
#include <cuda_runtime.h>

// ReluVerifier, terminal kernel. The reference's O(N^2) structure collapses
// exactly: the AlgebraicBound is identity-initialized, so Ip = I, In = 0, and
// every mult matrix is diagonal -> the whole backward pass is elementwise.
//
//   slope  = max(ub/(ub-lb), 0)            (ub-lb > 0 guaranteed)
//   d_ub   = lb>0 ? 1 : slope
//   d_lb   = ub<0 ? 0 : (lb>0 ? 1 : sigmoid(alpha))
//   ubias  = lb>0 ? 0 : -slope*lb
//   out_ub = ubias + max(d_ub,0)*ub + min(d_ub,0)*lb
//   out_lb =         max(d_lb,0)*lb + min(d_lb,0)*ub
//
// 4096 elems = 1024 float4 lanes, one launch, one wave, fully coalesced.
// Evidence R1-R11: every ncu pipe <0.5% under every variant tried; this
// exact binary benches {4.576, 4.608 x3, 4.832, 4.992, 5.632, 6.880}us
// across eight holds while ncu kernel time reads 4.0-4.5us. The harness dur
// is a bimodal (~4.6 vs ~6.9) code-independent draw — submit/replay/DVFS
// state, outside the .cu. This kernel is at the work floor; held fixed.

static constexpr int N = 4096;

__global__ __launch_bounds__(128)
void relu_verifier_kernel(const float4* __restrict__ lb4,
                          const float4* __restrict__ ub4,
                          const float4* __restrict__ al4,
                          float* __restrict__ out) {
    int i = blockIdx.x * 128 + threadIdx.x;  // 0..1023 exact, no bounds check

    float4* out_ub4 = reinterpret_cast<float4*>(out);
    float4* out_lb4 = reinterpret_cast<float4*>(out + N);

    float4 lb = lb4[i];
    float4 ub = ub4[i];
    float4 al = al4[i];

    float oub[4], olb[4];
    const float* lbp = &lb.x;
    const float* ubp = &ub.x;
    const float* alp = &al.x;

#pragma unroll
    for (int k = 0; k < 4; k++) {
        float l = lbp[k], u = ubp[k], a = alp[k];
        float slope = fmaxf(__fdividef(u, u - l), 0.0f);
        float d_ub  = (l > 0.0f) ? 1.0f : slope;
        float sig   = __fdividef(1.0f, 1.0f + __expf(-a));
        float d_lb  = (u < 0.0f) ? 0.0f : ((l > 0.0f) ? 1.0f : sig);
        float ubias = (l > 0.0f) ? 0.0f : (-slope * l);

        oub[k] = ubias + fmaxf(d_ub, 0.0f) * u + fminf(d_ub, 0.0f) * l;
        olb[k] =         fmaxf(d_lb, 0.0f) * l + fminf(d_lb, 0.0f) * u;
    }

    out_ub4[i] = make_float4(oub[0], oub[1], oub[2], oub[3]);
    out_lb4[i] = make_float4(olb[0], olb[1], olb[2], olb[3]);
}

extern "C" void kernel_launch(void* const* d_in, const int* in_sizes, int n_in,
                              void* d_out, int out_size) {
    const float4* lb4 = (const float4*)d_in[0];
    const float4* ub4 = (const float4*)d_in[1];
    const float4* al4 = (const float4*)d_in[2];
    float* out = (float*)d_out;

    relu_verifier_kernel<<<8, 128>>>(lb4, ub4, al4, out);
}

// round 13
// speedup vs baseline: 1.2867x; 1.2867x over previous
#include <cuda_runtime.h>

// ReluVerifier, terminal kernel. The reference's O(N^2) structure collapses
// exactly: the AlgebraicBound is identity-initialized, so Ip = I, In = 0, and
// every mult matrix is diagonal -> the whole backward pass is elementwise.
//
//   slope  = max(ub/(ub-lb), 0)            (ub-lb > 0 guaranteed)
//   d_ub   = lb>0 ? 1 : slope
//   d_lb   = ub<0 ? 0 : (lb>0 ? 1 : sigmoid(alpha))
//   ubias  = lb>0 ? 0 : -slope*lb
//   out_ub = ubias + max(d_ub,0)*ub + min(d_ub,0)*lb
//   out_lb =         max(d_lb,0)*lb + min(d_lb,0)*ub
//
// 4096 elems = 1024 float4 lanes, one launch, one wave, fully coalesced.
// Evidence R1-R12: every ncu pipe <0.5% under every variant tried; this
// exact binary benches {4.576, 4.608 x3, 4.832, 4.992, 5.632, 5.888, 6.880}
// us across nine holds while ncu kernel time reads 4.0-4.5us. The harness
// dur is a code-independent draw (submit/replay/DVFS state), outside the
// .cu. This kernel is at the work floor; held fixed at the measured best.

static constexpr int N = 4096;

__global__ __launch_bounds__(128)
void relu_verifier_kernel(const float4* __restrict__ lb4,
                          const float4* __restrict__ ub4,
                          const float4* __restrict__ al4,
                          float* __restrict__ out) {
    int i = blockIdx.x * 128 + threadIdx.x;  // 0..1023 exact, no bounds check

    float4* out_ub4 = reinterpret_cast<float4*>(out);
    float4* out_lb4 = reinterpret_cast<float4*>(out + N);

    float4 lb = lb4[i];
    float4 ub = ub4[i];
    float4 al = al4[i];

    float oub[4], olb[4];
    const float* lbp = &lb.x;
    const float* ubp = &ub.x;
    const float* alp = &al.x;

#pragma unroll
    for (int k = 0; k < 4; k++) {
        float l = lbp[k], u = ubp[k], a = alp[k];
        float slope = fmaxf(__fdividef(u, u - l), 0.0f);
        float d_ub  = (l > 0.0f) ? 1.0f : slope;
        float sig   = __fdividef(1.0f, 1.0f + __expf(-a));
        float d_lb  = (u < 0.0f) ? 0.0f : ((l > 0.0f) ? 1.0f : sig);
        float ubias = (l > 0.0f) ? 0.0f : (-slope * l);

        oub[k] = ubias + fmaxf(d_ub, 0.0f) * u + fminf(d_ub, 0.0f) * l;
        olb[k] =         fmaxf(d_lb, 0.0f) * l + fminf(d_lb, 0.0f) * u;
    }

    out_ub4[i] = make_float4(oub[0], oub[1], oub[2], oub[3]);
    out_lb4[i] = make_float4(olb[0], olb[1], olb[2], olb[3]);
}

extern "C" void kernel_launch(void* const* d_in, const int* in_sizes, int n_in,
                              void* d_out, int out_size) {
    const float4* lb4 = (const float4*)d_in[0];
    const float4* ub4 = (const float4*)d_in[1];
    const float4* al4 = (const float4*)d_in[2];
    float* out = (float*)d_out;

    relu_verifier_kernel<<<8, 128>>>(lb4, ub4, al4, out);
}